// round 15
// baseline (speedup 1.0000x reference)
#include <cuda_runtime.h>
#include <cuda_fp16.h>
#include <math.h>
#include <stdint.h>

// Problem dims (fixed by the dataset)
#define MDIM  8192
#define NBANK 8192
#define KDIM  1024
#define ODIM  1024
#define G1_GRIDN 64   // NBANK / 128
#define KSPLIT 4
#define KCHUNK (NBANK / KSPLIT)   // 2048

// ---------------- scratch (static device globals; no allocs) ----------------
__device__ __half g_qh [(size_t)MDIM  * KDIM ];
__device__ __half g_kh [(size_t)NBANK * KDIM ];
__device__ __half g_vhT[(size_t)ODIM  * NBANK];
__device__ __half g_Sh [(size_t)MDIM  * NBANK];   // scores fp16 (134 MB)
__device__ __half g_G  [(size_t)MDIM  * NBANK];   // gated fp16  (134 MB)
__device__ float  g_p2 [(size_t)KSPLIT * MDIM * ODIM];  // split-K partials (128 MB)
__device__ float  g_partials[(size_t)MDIM * G1_GRIDN];
__device__ float  g_invnorm [MDIM];

// ---------------- PTX helpers ----------------
__device__ __forceinline__ uint32_t smem_u32(const void* p) {
    uint32_t a;
    asm("{ .reg .u64 t; cvta.to.shared.u64 t, %1; cvt.u32.u64 %0, t; }" : "=r"(a) : "l"(p));
    return a;
}
__device__ __forceinline__ void cp_async16(uint32_t s, const void* g) {
    asm volatile("cp.async.cg.shared.global [%0], [%1], 16;\n" :: "r"(s), "l"(g));
}
__device__ __forceinline__ void cp_commit() { asm volatile("cp.async.commit_group;\n"); }
__device__ __forceinline__ void cp_wait0()  { asm volatile("cp.async.wait_group 0;\n"); }
__device__ __forceinline__ void cp_wait1()  { asm volatile("cp.async.wait_group 1;\n"); }

__device__ __forceinline__ void ldsm4(uint32_t& r0, uint32_t& r1, uint32_t& r2, uint32_t& r3,
                                      uint32_t addr) {
    asm volatile("ldmatrix.sync.aligned.m8n8.x4.shared.b16 {%0,%1,%2,%3}, [%4];\n"
                 : "=r"(r0), "=r"(r1), "=r"(r2), "=r"(r3) : "r"(addr));
}
__device__ __forceinline__ void mma16816(float c[4], uint32_t a0, uint32_t a1, uint32_t a2,
                                         uint32_t a3, uint32_t b0, uint32_t b1) {
    asm("mma.sync.aligned.m16n8k16.row.col.f32.f16.f16.f32 "
        "{%0,%1,%2,%3}, {%4,%5,%6,%7}, {%8,%9}, {%0,%1,%2,%3};\n"
        : "+f"(c[0]), "+f"(c[1]), "+f"(c[2]), "+f"(c[3])
        : "r"(a0), "r"(a1), "r"(a2), "r"(a3), "r"(b0), "r"(b1));
}

// SW128 swizzle for 128-byte rows: XOR row parity into byte-col bits [6:4]
#define SW128(off) ((off) ^ (((off) >> 3) & 0x70))

#define BM 128
#define BN 128
#define BK 64
#define STAGES 3
#define STAGE_BYTES (BM * BK * 2)              // 16384 (same for A and B)
#define SMEM_BYTES (STAGES * 2 * STAGE_BYTES)  // 98304

// ---------------- kernel 0a: fp32 -> fp16 copy ----------------
__global__ void f2h_kernel(const float4* __restrict__ src, uint2* __restrict__ dst, int n4) {
    int i = blockIdx.x * blockDim.x + threadIdx.x;
    if (i >= n4) return;
    float4 v = src[i];
    __half2 h0 = __floats2half2_rn(v.x, v.y);
    __half2 h1 = __floats2half2_rn(v.z, v.w);
    uint2 o;
    o.x = *reinterpret_cast<unsigned*>(&h0);
    o.y = *reinterpret_cast<unsigned*>(&h1);
    dst[i] = o;
}

// ---------------- kernel 0b: v [NBANK][ODIM] -> fp16 vT [ODIM][NBANK] ----------------
__global__ void transpose_f2h_kernel(const float* __restrict__ v, __half* __restrict__ vt) {
    __shared__ float tile[32][33];
    int bx = blockIdx.x * 32;
    int by = blockIdx.y * 32;
    int tx = threadIdx.x, ty = threadIdx.y;
#pragma unroll
    for (int j = 0; j < 32; j += 8)
        tile[ty + j][tx] = v[(size_t)(by + ty + j) * ODIM + bx + tx];
    __syncthreads();
#pragma unroll
    for (int j = 0; j < 32; j += 8)
        vt[(size_t)(bx + ty + j) * NBANK + by + tx] = __float2half(tile[tx][ty + j]);
}

// ---------------- GEMM1: Sh = fp16(q * k^T) + sumsq partials (UNCHANGED) --------------
__global__ void __launch_bounds__(256, 2) gemm1_kernel(
    const __half* __restrict__ A, const __half* __restrict__ B, __half* __restrict__ C,
    int K, int N, float* __restrict__ partials, int gridN) {
    extern __shared__ char smem[];
    const uint32_t sm = smem_u32(smem);
    const uint32_t smA = sm;
    const uint32_t smB = sm + STAGES * STAGE_BYTES;

    const int tid = threadIdx.x, lane = tid & 31, wid = tid >> 5;
    const int wm = wid >> 2, wn = wid & 3;
    const int bm = blockIdx.y * BM, bn = blockIdx.x * BN;

    float c[4][4][4];
#pragma unroll
    for (int a = 0; a < 4; a++)
#pragma unroll
        for (int b = 0; b < 4; b++)
#pragma unroll
            for (int i = 0; i < 4; i++) c[a][b][i] = 0.f;

    auto load_stage = [&](int s, int k0) {
        const uint32_t aBase = smA + s * STAGE_BYTES;
        const uint32_t bBase = smB + s * STAGE_BYTES;
#pragma unroll
        for (int i = 0; i < 4; i++) {
            int ch = tid + i * 256;
            int r = ch >> 3;
            int cb = (ch & 7) * 16;
            uint32_t ph = SW128((uint32_t)(r * 128 + cb));
            cp_async16(aBase + ph, A + (size_t)(bm + r) * K + k0 + (ch & 7) * 8);
            cp_async16(bBase + ph, B + (size_t)(bn + r) * K + k0 + (ch & 7) * 8);
        }
        cp_commit();
    };

    const int lr = lane & 15;
    const uint32_t hi = (uint32_t)(lane >> 4) * 16;
    const int rowA = wm * 64 + lr;
    const uint32_t swA = ((uint32_t)rowA & 7) << 4;
    const uint32_t aRow = smA + rowA * 128;
    const int rowB = wn * 32 + lr;
    const uint32_t swB = ((uint32_t)rowB & 7) << 4;
    const uint32_t bRow = smB + rowB * 128;

    const int NT = K / BK;
    load_stage(0, 0);
    load_stage(1, BK);

    for (int kt = 0; kt < NT; ++kt) {
        if (kt + 1 < NT) cp_wait1(); else cp_wait0();
        __syncthreads();
        if (kt + 2 < NT) load_stage((kt + 2) % STAGES, (kt + 2) * BK);

        const int s = kt % STAGES;
        const uint32_t aS = aRow + s * STAGE_BYTES;
        const uint32_t bS = bRow + s * STAGE_BYTES;
#pragma unroll
        for (int ks = 0; ks < 4; ++ks) {
            const uint32_t col = (uint32_t)(ks * 32) + hi;
            uint32_t a[4][4], b[4][2];
#pragma unroll
            for (int mt = 0; mt < 4; ++mt)
                ldsm4(a[mt][0], a[mt][1], a[mt][2], a[mt][3],
                      aS + mt * 2048 + (col ^ swA));
#pragma unroll
            for (int bt = 0; bt < 2; ++bt) {
                uint32_t t0, t1, t2, t3;
                ldsm4(t0, t1, t2, t3, bS + bt * 2048 + (col ^ swB));
                b[bt * 2 + 0][0] = t0; b[bt * 2 + 0][1] = t2;
                b[bt * 2 + 1][0] = t1; b[bt * 2 + 1][1] = t3;
            }
#pragma unroll
            for (int mt = 0; mt < 4; ++mt)
#pragma unroll
                for (int nt = 0; nt < 4; ++nt)
                    mma16816(c[mt][nt], a[mt][0], a[mt][1], a[mt][2], a[mt][3],
                             b[nt][0], b[nt][1]);
        }
    }

    const int rowBase = bm + wm * 64;
    const int colBase = bn + wn * 32;
#pragma unroll
    for (int mt = 0; mt < 4; ++mt) {
#pragma unroll
        for (int nt = 0; nt < 4; ++nt) {
            int row = rowBase + mt * 16 + (lane >> 2);
            int col = colBase + nt * 8 + (lane & 3) * 2;
            __half2* p0 = reinterpret_cast<__half2*>(C + (size_t)row * N + col);
            __half2* p1 = reinterpret_cast<__half2*>(C + (size_t)(row + 8) * N + col);
            *p0 = __floats2half2_rn(c[mt][nt][0], c[mt][nt][1]);
            *p1 = __floats2half2_rn(c[mt][nt][2], c[mt][nt][3]);
        }
    }

    {   // sumsq epilogue
        float acc[4][2];
#pragma unroll
        for (int mt = 0; mt < 4; ++mt) { acc[mt][0] = 0.f; acc[mt][1] = 0.f; }
#pragma unroll
        for (int mt = 0; mt < 4; ++mt)
#pragma unroll
            for (int nt = 0; nt < 4; ++nt) {
                acc[mt][0] += c[mt][nt][0] * c[mt][nt][0] + c[mt][nt][1] * c[mt][nt][1];
                acc[mt][1] += c[mt][nt][2] * c[mt][nt][2] + c[mt][nt][3] * c[mt][nt][3];
            }
#pragma unroll
        for (int o = 1; o < 4; o <<= 1)
#pragma unroll
            for (int mt = 0; mt < 4; ++mt) {
                acc[mt][0] += __shfl_xor_sync(0xffffffffu, acc[mt][0], o);
                acc[mt][1] += __shfl_xor_sync(0xffffffffu, acc[mt][1], o);
            }
        float* red = reinterpret_cast<float*>(smem);
        __syncthreads();
        if ((lane & 3) == 0) {
            int rq = lane >> 2;
#pragma unroll
            for (int mt = 0; mt < 4; ++mt) {
                red[wn * 128 + wm * 64 + mt * 16 + rq]     = acc[mt][0];
                red[wn * 128 + wm * 64 + mt * 16 + 8 + rq] = acc[mt][1];
            }
        }
        __syncthreads();
        if (tid < BM) {
            float s = red[tid] + red[128 + tid] + red[256 + tid] + red[384 + tid];
            partials[(size_t)(bm + tid) * gridN + blockIdx.x] = s;
        }
    }
}

// ---------------- GEMM2: static split-K=4, all dims compile-time ----------------------
// P2[z] = G[:, z*2048:(z+1)*2048] * vT[:, z*2048:(z+1)*2048]^T
// Grid (8, 64, 4): 2048 CTAs -> 7 waves at 2 CTAs/SM, ~1.2% quantization idle.
__global__ void __launch_bounds__(256, 2) gemm2_kernel(
    const __half* __restrict__ A, const __half* __restrict__ B, float* __restrict__ P2) {
    extern __shared__ char smem[];
    const uint32_t sm = smem_u32(smem);
    const uint32_t smA = sm;
    const uint32_t smB = sm + STAGES * STAGE_BYTES;

    const int tid = threadIdx.x, lane = tid & 31, wid = tid >> 5;
    const int wm = wid >> 2, wn = wid & 3;
    const int bm = blockIdx.y * BM, bn = blockIdx.x * BN;

    // split-K chunk: resolved once, before the hot loop; everything else static
    A += (size_t)blockIdx.z * KCHUNK;
    B += (size_t)blockIdx.z * KCHUNK;
    P2 += (size_t)blockIdx.z * ((size_t)MDIM * ODIM);

    float c[4][4][4];
#pragma unroll
    for (int a = 0; a < 4; a++)
#pragma unroll
        for (int b = 0; b < 4; b++)
#pragma unroll
            for (int i = 0; i < 4; i++) c[a][b][i] = 0.f;

    auto load_stage = [&](int s, int k0) {
        const uint32_t aBase = smA + s * STAGE_BYTES;
        const uint32_t bBase = smB + s * STAGE_BYTES;
#pragma unroll
        for (int i = 0; i < 4; i++) {
            int ch = tid + i * 256;
            int r = ch >> 3;
            int cb = (ch & 7) * 16;
            uint32_t ph = SW128((uint32_t)(r * 128 + cb));
            cp_async16(aBase + ph, A + (size_t)(bm + r) * NBANK + k0 + (ch & 7) * 8);
            cp_async16(bBase + ph, B + (size_t)(bn + r) * NBANK + k0 + (ch & 7) * 8);
        }
        cp_commit();
    };

    const int lr = lane & 15;
    const uint32_t hi = (uint32_t)(lane >> 4) * 16;
    const int rowA = wm * 64 + lr;
    const uint32_t swA = ((uint32_t)rowA & 7) << 4;
    const uint32_t aRow = smA + rowA * 128;
    const int rowB = wn * 32 + lr;
    const uint32_t swB = ((uint32_t)rowB & 7) << 4;
    const uint32_t bRow = smB + rowB * 128;

    const int NT = KCHUNK / BK;   // 32, compile-time
    load_stage(0, 0);
    load_stage(1, BK);

    for (int kt = 0; kt < NT; ++kt) {
        if (kt + 1 < NT) cp_wait1(); else cp_wait0();
        __syncthreads();
        if (kt + 2 < NT) load_stage((kt + 2) % STAGES, (kt + 2) * BK);

        const int s = kt % STAGES;
        const uint32_t aS = aRow + s * STAGE_BYTES;
        const uint32_t bS = bRow + s * STAGE_BYTES;
#pragma unroll
        for (int ks = 0; ks < 4; ++ks) {
            const uint32_t col = (uint32_t)(ks * 32) + hi;
            uint32_t a[4][4], b[4][2];
#pragma unroll
            for (int mt = 0; mt < 4; ++mt)
                ldsm4(a[mt][0], a[mt][1], a[mt][2], a[mt][3],
                      aS + mt * 2048 + (col ^ swA));
#pragma unroll
            for (int bt = 0; bt < 2; ++bt) {
                uint32_t t0, t1, t2, t3;
                ldsm4(t0, t1, t2, t3, bS + bt * 2048 + (col ^ swB));
                b[bt * 2 + 0][0] = t0; b[bt * 2 + 0][1] = t2;
                b[bt * 2 + 1][0] = t1; b[bt * 2 + 1][1] = t3;
            }
#pragma unroll
            for (int mt = 0; mt < 4; ++mt)
#pragma unroll
                for (int nt = 0; nt < 4; ++nt)
                    mma16816(c[mt][nt], a[mt][0], a[mt][1], a[mt][2], a[mt][3],
                             b[nt][0], b[nt][1]);
        }
    }

    const int rowBase = bm + wm * 64;
    const int colBase = bn + wn * 32;
#pragma unroll
    for (int mt = 0; mt < 4; ++mt) {
#pragma unroll
        for (int nt = 0; nt < 4; ++nt) {
            int row = rowBase + mt * 16 + (lane >> 2);
            int col = colBase + nt * 8 + (lane & 3) * 2;
            float2* p0 = reinterpret_cast<float2*>(P2 + (size_t)row * ODIM + col);
            float2* p1 = reinterpret_cast<float2*>(P2 + (size_t)(row + 8) * ODIM + col);
            *p0 = make_float2(c[mt][nt][0], c[mt][nt][1]);
            *p1 = make_float2(c[mt][nt][2], c[mt][nt][3]);
        }
    }
}

// ---------------- kernel 5: out = fixed-order sum of 4 split planes ----------------
__global__ void combine_kernel(const float4* __restrict__ p, float4* __restrict__ out, int n4) {
    int i = blockIdx.x * blockDim.x + threadIdx.x;
    if (i >= n4) return;
    const int stride4 = MDIM * ODIM / 4;
    float4 a = p[i];
    float4 b = p[i + stride4];
    float4 c = p[i + 2 * stride4];
    float4 d = p[i + 3 * stride4];
    float4 o;
    o.x = (a.x + b.x) + (c.x + d.x);
    o.y = (a.y + b.y) + (c.y + d.y);
    o.z = (a.z + b.z) + (c.z + d.z);
    o.w = (a.w + b.w) + (c.w + d.w);
    out[i] = o;
}

// ---------------- kernel 2: row norms ----------------
__global__ void rownorm_kernel(const float* __restrict__ partials, float* __restrict__ invnorm,
                               int gridN) {
    int row = blockIdx.x * blockDim.x + threadIdx.x;
    if (row >= MDIM) return;
    float s = 0.f;
    for (int j = 0; j < gridN; j++) s += partials[(size_t)row * gridN + j];
    invnorm[row] = sqrtf((float)NBANK) * rsqrtf(s);
}

// ---------------- kernel 3: G = fp16(gelu(Sh * invnorm[row])), 8 halves/thread --------
__global__ void gelu_kernel(const uint4* __restrict__ S, uint4* __restrict__ G,
                            const float* __restrict__ invnorm, int n8) {
    int i = blockIdx.x * blockDim.x + threadIdx.x;
    if (i >= n8) return;
    float sc = invnorm[i >> 10];  // NBANK/8 = 1024 uint4 per row
    uint4 x = S[i];
    uint4 o;
    unsigned* xi = reinterpret_cast<unsigned*>(&x);
    unsigned* oi = reinterpret_cast<unsigned*>(&o);
#pragma unroll
    for (int j = 0; j < 4; j++) {
        __half2 h = *reinterpret_cast<__half2*>(&xi[j]);
        float a0 = __low2float(h) * sc;
        float a1 = __high2float(h) * sc;
        float g0 = a0 * normcdff(a0);  // exact GELU: x * Phi(x)
        float g1 = a1 * normcdff(a1);
        __half2 r = __floats2half2_rn(g0, g1);
        oi[j] = *reinterpret_cast<unsigned*>(&r);
    }
    G[i] = o;
}

// ---------------- launch ----------------
extern "C" void kernel_launch(void* const* d_in, const int* in_sizes, int n_in,
                              void* d_out, int out_size) {
    const float* q = (const float*)d_in[0];
    const float* k = (const float*)d_in[1];
    const float* v = (const float*)d_in[2];
    float* out = (float*)d_out;

    __half *qh, *kh, *vt, *Sh, *G;
    float *p2, *partials, *invn;
    cudaGetSymbolAddress((void**)&qh, g_qh);
    cudaGetSymbolAddress((void**)&kh, g_kh);
    cudaGetSymbolAddress((void**)&vt, g_vhT);
    cudaGetSymbolAddress((void**)&Sh, g_Sh);
    cudaGetSymbolAddress((void**)&G, g_G);
    cudaGetSymbolAddress((void**)&p2, g_p2);
    cudaGetSymbolAddress((void**)&partials, g_partials);
    cudaGetSymbolAddress((void**)&invn, g_invnorm);

    cudaFuncSetAttribute((const void*)gemm1_kernel,
                         cudaFuncAttributeMaxDynamicSharedMemorySize, SMEM_BYTES);
    cudaFuncSetAttribute((const void*)gemm2_kernel,
                         cudaFuncAttributeMaxDynamicSharedMemorySize, SMEM_BYTES);

    // 0) input conversion
    const int QN4 = MDIM * KDIM / 4;
    const int KN4 = NBANK * KDIM / 4;
    f2h_kernel<<<(QN4 + 255) / 256, 256>>>((const float4*)q, (uint2*)qh, QN4);
    f2h_kernel<<<(KN4 + 255) / 256, 256>>>((const float4*)k, (uint2*)kh, KN4);
    transpose_f2h_kernel<<<dim3(ODIM / 32, NBANK / 32), dim3(32, 8)>>>(v, vt);

    // 1) Sh = fp16(q * k^T), + per-tile sumsq partials (from fp32 accumulators)
    gemm1_kernel<<<dim3(NBANK / BN, MDIM / BM), 256, SMEM_BYTES>>>(
        qh, kh, Sh, KDIM, NBANK, partials, G1_GRIDN);

    // 2) row inverse norms (deterministic fixed-order sum)
    rownorm_kernel<<<MDIM / 256, 256>>>(partials, invn, G1_GRIDN);

    // 3) G = fp16(gelu(Sh * invnorm))
    const int SN8 = (int)((size_t)MDIM * NBANK / 8);
    gelu_kernel<<<(SN8 + 255) / 256, 256>>>((const uint4*)Sh, (uint4*)G, invn, SN8);

    // 4) split-K GEMM2: 4 planes of partials (static kernel, 7 full waves)
    gemm2_kernel<<<dim3(ODIM / BN, MDIM / BM, KSPLIT), 256, SMEM_BYTES>>>(G, vt, p2);

    // 5) out = p2[0]+p2[1]+p2[2]+p2[3] (fixed order -> deterministic)
    const int ON4 = MDIM * ODIM / 4;
    combine_kernel<<<(ON4 + 255) / 256, 256>>>((const float4*)p2, (float4*)out, ON4);
}

// round 16
// speedup vs baseline: 1.0092x; 1.0092x over previous
#include <cuda_runtime.h>
#include <cuda_fp16.h>
#include <math.h>
#include <stdint.h>

// Problem dims (fixed by the dataset)
#define MDIM  8192
#define NBANK 8192
#define KDIM  1024
#define ODIM  1024
#define G1_GRIDN 64   // NBANK / 128
#define G2_TILES 512  // (MDIM/128) * (ODIM/128)
#define G2_UNITS ((long long)G2_TILES * 128)  // 65536 kt units (BK=64)

// ---------------- scratch (static device globals; no allocs) ----------------
__device__ __half g_qh [(size_t)MDIM  * KDIM ];
__device__ __half g_kh [(size_t)NBANK * KDIM ];
__device__ __half g_vhT[(size_t)ODIM  * NBANK];
__device__ __half g_Sh [(size_t)MDIM  * NBANK];   // scores fp16 (134 MB)
__device__ __half g_G  [(size_t)MDIM  * NBANK];   // gated fp16  (134 MB)
__device__ float  g_p1 [(size_t)MDIM * ODIM];     // GEMM2 second-coverer partials (32 MB)
__device__ float  g_partials[(size_t)MDIM * G1_GRIDN];
__device__ float  g_invnorm [MDIM];

// ---------------- PTX helpers ----------------
__device__ __forceinline__ uint32_t smem_u32(const void* p) {
    uint32_t a;
    asm("{ .reg .u64 t; cvta.to.shared.u64 t, %1; cvt.u32.u64 %0, t; }" : "=r"(a) : "l"(p));
    return a;
}
__device__ __forceinline__ void cp_async16(uint32_t s, const void* g) {
    asm volatile("cp.async.cg.shared.global [%0], [%1], 16;\n" :: "r"(s), "l"(g));
}
__device__ __forceinline__ void cp_commit() { asm volatile("cp.async.commit_group;\n"); }
__device__ __forceinline__ void cp_wait0()  { asm volatile("cp.async.wait_group 0;\n"); }
__device__ __forceinline__ void cp_wait1()  { asm volatile("cp.async.wait_group 1;\n"); }

__device__ __forceinline__ void ldsm4(uint32_t& r0, uint32_t& r1, uint32_t& r2, uint32_t& r3,
                                      uint32_t addr) {
    asm volatile("ldmatrix.sync.aligned.m8n8.x4.shared.b16 {%0,%1,%2,%3}, [%4];\n"
                 : "=r"(r0), "=r"(r1), "=r"(r2), "=r"(r3) : "r"(addr));
}
__device__ __forceinline__ void mma16816(float c[4], uint32_t a0, uint32_t a1, uint32_t a2,
                                         uint32_t a3, uint32_t b0, uint32_t b1) {
    asm("mma.sync.aligned.m16n8k16.row.col.f32.f16.f16.f32 "
        "{%0,%1,%2,%3}, {%4,%5,%6,%7}, {%8,%9}, {%0,%1,%2,%3};\n"
        : "+f"(c[0]), "+f"(c[1]), "+f"(c[2]), "+f"(c[3])
        : "r"(a0), "r"(a1), "r"(a2), "r"(a3), "r"(b0), "r"(b1));
}

// SW128 swizzle for 128-byte rows: XOR row parity into byte-col bits [6:4]
#define SW128(off) ((off) ^ (((off) >> 3) & 0x70))

#define BM 128
#define BN 128
#define BK 64
#define STAGES 3
#define STAGE_BYTES (BM * BK * 2)              // 16384 (same for A and B)
#define SMEM_BYTES (STAGES * 2 * STAGE_BYTES)  // 98304

// ---------------- kernel 0a: fp32 -> fp16 copy ----------------
__global__ void f2h_kernel(const float4* __restrict__ src, uint2* __restrict__ dst, int n4) {
    int i = blockIdx.x * blockDim.x + threadIdx.x;
    if (i >= n4) return;
    float4 v = src[i];
    __half2 h0 = __floats2half2_rn(v.x, v.y);
    __half2 h1 = __floats2half2_rn(v.z, v.w);
    uint2 o;
    o.x = *reinterpret_cast<unsigned*>(&h0);
    o.y = *reinterpret_cast<unsigned*>(&h1);
    dst[i] = o;
}

// ---------------- kernel 0b: v [NBANK][ODIM] -> fp16 vT [ODIM][NBANK] ----------------
__global__ void transpose_f2h_kernel(const float* __restrict__ v, __half* __restrict__ vt) {
    __shared__ float tile[32][33];
    int bx = blockIdx.x * 32;
    int by = blockIdx.y * 32;
    int tx = threadIdx.x, ty = threadIdx.y;
#pragma unroll
    for (int j = 0; j < 32; j += 8)
        tile[ty + j][tx] = v[(size_t)(by + ty + j) * ODIM + bx + tx];
    __syncthreads();
#pragma unroll
    for (int j = 0; j < 32; j += 8)
        vt[(size_t)(bx + ty + j) * NBANK + by + tx] = __float2half(tile[tx][ty + j]);
}

// ---------------- GEMM1: Sh = fp16(q * k^T) + sumsq partials (UNCHANGED from R14) -----
__global__ void __launch_bounds__(256, 2) gemm1_kernel(
    const __half* __restrict__ A, const __half* __restrict__ B, __half* __restrict__ C,
    int K, int N, float* __restrict__ partials, int gridN) {
    extern __shared__ char smem[];
    const uint32_t sm = smem_u32(smem);
    const uint32_t smA = sm;
    const uint32_t smB = sm + STAGES * STAGE_BYTES;

    const int tid = threadIdx.x, lane = tid & 31, wid = tid >> 5;
    const int wm = wid >> 2, wn = wid & 3;
    const int bm = blockIdx.y * BM, bn = blockIdx.x * BN;

    float c[4][4][4];
#pragma unroll
    for (int a = 0; a < 4; a++)
#pragma unroll
        for (int b = 0; b < 4; b++)
#pragma unroll
            for (int i = 0; i < 4; i++) c[a][b][i] = 0.f;

    auto load_stage = [&](int s, int k0) {
        const uint32_t aBase = smA + s * STAGE_BYTES;
        const uint32_t bBase = smB + s * STAGE_BYTES;
#pragma unroll
        for (int i = 0; i < 4; i++) {
            int ch = tid + i * 256;
            int r = ch >> 3;
            int cb = (ch & 7) * 16;
            uint32_t ph = SW128((uint32_t)(r * 128 + cb));
            cp_async16(aBase + ph, A + (size_t)(bm + r) * K + k0 + (ch & 7) * 8);
            cp_async16(bBase + ph, B + (size_t)(bn + r) * K + k0 + (ch & 7) * 8);
        }
        cp_commit();
    };

    const int lr = lane & 15;
    const uint32_t hi = (uint32_t)(lane >> 4) * 16;
    const int rowA = wm * 64 + lr;
    const uint32_t swA = ((uint32_t)rowA & 7) << 4;
    const uint32_t aRow = smA + rowA * 128;
    const int rowB = wn * 32 + lr;
    const uint32_t swB = ((uint32_t)rowB & 7) << 4;
    const uint32_t bRow = smB + rowB * 128;

    const int NT = K / BK;
    load_stage(0, 0);
    load_stage(1, BK);

    for (int kt = 0; kt < NT; ++kt) {
        if (kt + 1 < NT) cp_wait1(); else cp_wait0();
        __syncthreads();
        if (kt + 2 < NT) load_stage((kt + 2) % STAGES, (kt + 2) * BK);

        const int s = kt % STAGES;
        const uint32_t aS = aRow + s * STAGE_BYTES;
        const uint32_t bS = bRow + s * STAGE_BYTES;
#pragma unroll
        for (int ks = 0; ks < 4; ++ks) {
            const uint32_t col = (uint32_t)(ks * 32) + hi;
            uint32_t a[4][4], b[4][2];
#pragma unroll
            for (int mt = 0; mt < 4; ++mt)
                ldsm4(a[mt][0], a[mt][1], a[mt][2], a[mt][3],
                      aS + mt * 2048 + (col ^ swA));
#pragma unroll
            for (int bt = 0; bt < 2; ++bt) {
                uint32_t t0, t1, t2, t3;
                ldsm4(t0, t1, t2, t3, bS + bt * 2048 + (col ^ swB));
                b[bt * 2 + 0][0] = t0; b[bt * 2 + 0][1] = t2;
                b[bt * 2 + 1][0] = t1; b[bt * 2 + 1][1] = t3;
            }
#pragma unroll
            for (int mt = 0; mt < 4; ++mt)
#pragma unroll
                for (int nt = 0; nt < 4; ++nt)
                    mma16816(c[mt][nt], a[mt][0], a[mt][1], a[mt][2], a[mt][3],
                             b[nt][0], b[nt][1]);
        }
    }

    const int rowBase = bm + wm * 64;
    const int colBase = bn + wn * 32;
#pragma unroll
    for (int mt = 0; mt < 4; ++mt) {
#pragma unroll
        for (int nt = 0; nt < 4; ++nt) {
            int row = rowBase + mt * 16 + (lane >> 2);
            int col = colBase + nt * 8 + (lane & 3) * 2;
            __half2* p0 = reinterpret_cast<__half2*>(C + (size_t)row * N + col);
            __half2* p1 = reinterpret_cast<__half2*>(C + (size_t)(row + 8) * N + col);
            *p0 = __floats2half2_rn(c[mt][nt][0], c[mt][nt][1]);
            *p1 = __floats2half2_rn(c[mt][nt][2], c[mt][nt][3]);
        }
    }

    {   // sumsq epilogue
        float acc[4][2];
#pragma unroll
        for (int mt = 0; mt < 4; ++mt) { acc[mt][0] = 0.f; acc[mt][1] = 0.f; }
#pragma unroll
        for (int mt = 0; mt < 4; ++mt)
#pragma unroll
            for (int nt = 0; nt < 4; ++nt) {
                acc[mt][0] += c[mt][nt][0] * c[mt][nt][0] + c[mt][nt][1] * c[mt][nt][1];
                acc[mt][1] += c[mt][nt][2] * c[mt][nt][2] + c[mt][nt][3] * c[mt][nt][3];
            }
#pragma unroll
        for (int o = 1; o < 4; o <<= 1)
#pragma unroll
            for (int mt = 0; mt < 4; ++mt) {
                acc[mt][0] += __shfl_xor_sync(0xffffffffu, acc[mt][0], o);
                acc[mt][1] += __shfl_xor_sync(0xffffffffu, acc[mt][1], o);
            }
        float* red = reinterpret_cast<float*>(smem);
        __syncthreads();
        if ((lane & 3) == 0) {
            int rq = lane >> 2;
#pragma unroll
            for (int mt = 0; mt < 4; ++mt) {
                red[wn * 128 + wm * 64 + mt * 16 + rq]     = acc[mt][0];
                red[wn * 128 + wm * 64 + mt * 16 + 8 + rq] = acc[mt][1];
            }
        }
        __syncthreads();
        if (tid < BM) {
            float s = red[tid] + red[128 + tid] + red[256 + tid] + red[384 + tid];
            partials[(size_t)(bm + tid) * gridN + blockIdx.x] = s;
        }
    }
}

// ---------------- GEMM2: persistent, statically balanced (UNCHANGED from R14) ---------
__global__ void __launch_bounds__(256, 2) gemm2_persist_kernel(
    const __half* __restrict__ A, const __half* __restrict__ B,
    float* __restrict__ OUT, float* __restrict__ P1, int P) {
    extern __shared__ char smem[];
    const uint32_t sm = smem_u32(smem);
    const uint32_t smA = sm;
    const uint32_t smB = sm + STAGES * STAGE_BYTES;

    const int tid = threadIdx.x, lane = tid & 31, wid = tid >> 5;
    const int wm = wid >> 2, wn = wid & 3;

    const int lr = lane & 15;
    const uint32_t hi = (uint32_t)(lane >> 4) * 16;
    const int rowAl = wm * 64 + lr;
    const uint32_t swA = ((uint32_t)rowAl & 7) << 4;
    const uint32_t aRow = smA + rowAl * 128;
    const int rowBl = wn * 32 + lr;
    const uint32_t swB = ((uint32_t)rowBl & 7) << 4;
    const uint32_t bRow = smB + rowBl * 128;

    long long u0 = (G2_UNITS * blockIdx.x) / P;
    const long long u1 = (G2_UNITS * (blockIdx.x + 1)) / P;

    while (u0 < u1) {
        const int t   = (int)(u0 >> 7);
        const int k0  = (int)(u0 & 127);
        int nkt = 128 - k0;
        if (u0 + nkt > u1) nkt = (int)(u1 - u0);
        const int bm = (t >> 3) * BM;
        const int bn = (t & 7) * BN;
        const __half* Aseg = A + (size_t)k0 * BK;
        const __half* Bseg = B + (size_t)k0 * BK;

        float c[4][4][4];
#pragma unroll
        for (int a = 0; a < 4; a++)
#pragma unroll
            for (int b = 0; b < 4; b++)
#pragma unroll
                for (int i = 0; i < 4; i++) c[a][b][i] = 0.f;

        auto load_stage = [&](int s, int kk) {
            const uint32_t aBase = smA + s * STAGE_BYTES;
            const uint32_t bBase = smB + s * STAGE_BYTES;
#pragma unroll
            for (int i = 0; i < 4; i++) {
                int ch = tid + i * 256;
                int r = ch >> 3;
                int cb = (ch & 7) * 16;
                uint32_t ph = SW128((uint32_t)(r * 128 + cb));
                cp_async16(aBase + ph, Aseg + (size_t)(bm + r) * NBANK + kk * BK + (ch & 7) * 8);
                cp_async16(bBase + ph, Bseg + (size_t)(bn + r) * NBANK + kk * BK + (ch & 7) * 8);
            }
            cp_commit();
        };

        load_stage(0, 0);
        if (nkt > 1) load_stage(1, 1);

        for (int kt = 0; kt < nkt; ++kt) {
            if (kt + 1 < nkt) cp_wait1(); else cp_wait0();
            __syncthreads();
            if (kt + 2 < nkt) load_stage((kt + 2) % STAGES, kt + 2);

            const int s = kt % STAGES;
            const uint32_t aS = aRow + s * STAGE_BYTES;
            const uint32_t bS = bRow + s * STAGE_BYTES;
#pragma unroll
            for (int ks = 0; ks < 4; ++ks) {
                const uint32_t col = (uint32_t)(ks * 32) + hi;
                uint32_t a[4][4], b[4][2];
#pragma unroll
                for (int mt = 0; mt < 4; ++mt)
                    ldsm4(a[mt][0], a[mt][1], a[mt][2], a[mt][3],
                          aS + mt * 2048 + (col ^ swA));
#pragma unroll
                for (int bt = 0; bt < 2; ++bt) {
                    uint32_t t0, t1, t2, t3;
                    ldsm4(t0, t1, t2, t3, bS + bt * 2048 + (col ^ swB));
                    b[bt * 2 + 0][0] = t0; b[bt * 2 + 0][1] = t2;
                    b[bt * 2 + 1][0] = t1; b[bt * 2 + 1][1] = t3;
                }
#pragma unroll
                for (int mt = 0; mt < 4; ++mt)
#pragma unroll
                    for (int nt = 0; nt < 4; ++nt)
                        mma16816(c[mt][nt], a[mt][0], a[mt][1], a[mt][2], a[mt][3],
                                 b[nt][0], b[nt][1]);
            }
        }
        __syncthreads();  // smem reuse safety before next segment's loads

        // epilogue: k0==0 coverer -> OUT, k0>0 coverer -> P1 (read only for split tiles)
        float* D = (k0 == 0) ? OUT : P1;
        const int rowBase = bm + wm * 64;
        const int colBase = bn + wn * 32;
#pragma unroll
        for (int mt = 0; mt < 4; ++mt) {
#pragma unroll
            for (int nt = 0; nt < 4; ++nt) {
                int row = rowBase + mt * 16 + (lane >> 2);
                int col = colBase + nt * 8 + (lane & 3) * 2;
                float2* p0 = reinterpret_cast<float2*>(D + (size_t)row * ODIM + col);
                float2* p1 = reinterpret_cast<float2*>(D + (size_t)(row + 8) * ODIM + col);
                *p0 = make_float2(c[mt][nt][0], c[mt][nt][1]);
                *p1 = make_float2(c[mt][nt][2], c[mt][nt][3]);
            }
        }

        u0 += nkt;
    }
}

// ---------------- kernel 5: sparse out += P1 (only tiles split across two CTAs) -------
// CTA covering unit u is i(u) = (P*(u+1)-1) >> 16  (G2_UNITS = 65536).
// Tile t is split iff i(128t) != i(128t+127). Non-split tiles: untouched (no p1 read,
// no memset needed — their p1 region was never written and is never read).
__global__ void sparse_add_kernel(float4* __restrict__ out, const float4* __restrict__ p1,
                                  int P, int n4) {
    int i = blockIdx.x * blockDim.x + threadIdx.x;
    if (i >= n4) return;
    const int row = i >> 8;            // ODIM/4 = 256 float4 per row
    const int col4 = i & 255;
    const long long t = (long long)(row >> 7) * 8 + (col4 >> 5);
    const long long us = t << 7;
    const long long iA = ((long long)P * (us + 1) - 1) >> 16;
    const long long iB = ((long long)P * (us + 128) - 1) >> 16;
    if (iA == iB) return;              // tile fully covered by one CTA
    float4 a = out[i];
    float4 b = p1[i];
    a.x += b.x; a.y += b.y; a.z += b.z; a.w += b.w;
    out[i] = a;
}

// ---------------- kernel 2: row norms ----------------
__global__ void rownorm_kernel(const float* __restrict__ partials, float* __restrict__ invnorm,
                               int gridN) {
    int row = blockIdx.x * blockDim.x + threadIdx.x;
    if (row >= MDIM) return;
    float s = 0.f;
    for (int j = 0; j < gridN; j++) s += partials[(size_t)row * gridN + j];
    invnorm[row] = sqrtf((float)NBANK) * rsqrtf(s);
}

// ---------------- kernel 3: G = fp16(gelu(Sh * invnorm[row])), 8 halves/thread --------
__global__ void gelu_kernel(const uint4* __restrict__ S, uint4* __restrict__ G,
                            const float* __restrict__ invnorm, int n8) {
    int i = blockIdx.x * blockDim.x + threadIdx.x;
    if (i >= n8) return;
    float sc = invnorm[i >> 10];  // NBANK/8 = 1024 uint4 per row
    uint4 x = S[i];
    uint4 o;
    unsigned* xi = reinterpret_cast<unsigned*>(&x);
    unsigned* oi = reinterpret_cast<unsigned*>(&o);
#pragma unroll
    for (int j = 0; j < 4; j++) {
        __half2 h = *reinterpret_cast<__half2*>(&xi[j]);
        float a0 = __low2float(h) * sc;
        float a1 = __high2float(h) * sc;
        float g0 = a0 * normcdff(a0);  // exact GELU: x * Phi(x)
        float g1 = a1 * normcdff(a1);
        __half2 r = __floats2half2_rn(g0, g1);
        oi[j] = *reinterpret_cast<unsigned*>(&r);
    }
    G[i] = o;
}

// ---------------- launch ----------------
extern "C" void kernel_launch(void* const* d_in, const int* in_sizes, int n_in,
                              void* d_out, int out_size) {
    const float* q = (const float*)d_in[0];
    const float* k = (const float*)d_in[1];
    const float* v = (const float*)d_in[2];
    float* out = (float*)d_out;

    __half *qh, *kh, *vt, *Sh, *G;
    float *p1, *partials, *invn;
    cudaGetSymbolAddress((void**)&qh, g_qh);
    cudaGetSymbolAddress((void**)&kh, g_kh);
    cudaGetSymbolAddress((void**)&vt, g_vhT);
    cudaGetSymbolAddress((void**)&Sh, g_Sh);
    cudaGetSymbolAddress((void**)&G, g_G);
    cudaGetSymbolAddress((void**)&p1, g_p1);
    cudaGetSymbolAddress((void**)&partials, g_partials);
    cudaGetSymbolAddress((void**)&invn, g_invnorm);

    int nsm = 148;
    cudaDeviceGetAttribute(&nsm, cudaDevAttrMultiProcessorCount, 0);
    const int P = 2 * nsm;  // all persistent CTAs resident (2/SM)

    cudaFuncSetAttribute((const void*)gemm1_kernel,
                         cudaFuncAttributeMaxDynamicSharedMemorySize, SMEM_BYTES);
    cudaFuncSetAttribute((const void*)gemm2_persist_kernel,
                         cudaFuncAttributeMaxDynamicSharedMemorySize, SMEM_BYTES);

    // 0) input conversion
    const int QN4 = MDIM * KDIM / 4;
    const int KN4 = NBANK * KDIM / 4;
    f2h_kernel<<<(QN4 + 255) / 256, 256>>>((const float4*)q, (uint2*)qh, QN4);
    f2h_kernel<<<(KN4 + 255) / 256, 256>>>((const float4*)k, (uint2*)kh, KN4);
    transpose_f2h_kernel<<<dim3(ODIM / 32, NBANK / 32), dim3(32, 8)>>>(v, vt);

    // 1) Sh = fp16(q * k^T), + per-tile sumsq partials (from fp32 accumulators)
    gemm1_kernel<<<dim3(NBANK / BN, MDIM / BM), 256, SMEM_BYTES>>>(
        qh, kh, Sh, KDIM, NBANK, partials, G1_GRIDN);

    // 2) row inverse norms (deterministic fixed-order sum)
    rownorm_kernel<<<MDIM / 256, 256>>>(partials, invn, G1_GRIDN);

    // 3) G = fp16(gelu(Sh * invnorm))
    const int SN8 = (int)((size_t)MDIM * NBANK / 8);
    gelu_kernel<<<(SN8 + 255) / 256, 256>>>((const uint4*)Sh, (uint4*)G, invn, SN8);

    // 4) out/P1 = G * v (persistent, statically K-balanced; no memset needed)
    gemm2_persist_kernel<<<P, 256, SMEM_BYTES>>>(G, vt, out, p1, P);

    // 5) out += P1 for split tiles only (fixed order -> deterministic)
    const int ON4 = MDIM * ODIM / 4;
    sparse_add_kernel<<<(ON4 + 255) / 256, 256>>>((float4*)out, (const float4*)p1, P, ON4);
}

// round 17
// speedup vs baseline: 1.0225x; 1.0131x over previous
#include <cuda_runtime.h>
#include <cuda_fp16.h>
#include <math.h>
#include <stdint.h>

// Problem dims (fixed by the dataset)
#define MDIM  8192
#define NBANK 8192
#define KDIM  1024
#define ODIM  1024
#define G1_GRIDN 64   // NBANK / 128
#define G2_TILES 512  // (MDIM/128) * (ODIM/128)
#define G2_UNITS ((long long)G2_TILES * 128)  // 65536 kt units (BK=64)

// ---------------- scratch (static device globals; no allocs) ----------------
__device__ __half g_qh [(size_t)MDIM  * KDIM ];
__device__ __half g_kh [(size_t)NBANK * KDIM ];
__device__ __half g_vhT[(size_t)ODIM  * NBANK];
__device__ __half g_Sh [(size_t)MDIM  * NBANK];   // scores fp16 (134 MB)
__device__ __half g_G  [(size_t)MDIM  * NBANK];   // gated fp16  (134 MB)
__device__ float  g_partials[(size_t)MDIM * G1_GRIDN];
__device__ float  g_invnorm [MDIM];

// ---------------- PTX helpers ----------------
__device__ __forceinline__ uint32_t smem_u32(const void* p) {
    uint32_t a;
    asm("{ .reg .u64 t; cvta.to.shared.u64 t, %1; cvt.u32.u64 %0, t; }" : "=r"(a) : "l"(p));
    return a;
}
__device__ __forceinline__ void cp_async16(uint32_t s, const void* g) {
    asm volatile("cp.async.cg.shared.global [%0], [%1], 16;\n" :: "r"(s), "l"(g));
}
// GEMM2-only variant: prefetch the next 256B of the row into L2 (covers the next
// 1-2 kt of the sliding K window; A=G misses L2 on the leading edge otherwise).
__device__ __forceinline__ void cp_async16_pf(uint32_t s, const void* g) {
    asm volatile("cp.async.cg.shared.global.L2::256B [%0], [%1], 16;\n" :: "r"(s), "l"(g));
}
__device__ __forceinline__ void cp_commit() { asm volatile("cp.async.commit_group;\n"); }
__device__ __forceinline__ void cp_wait0()  { asm volatile("cp.async.wait_group 0;\n"); }
__device__ __forceinline__ void cp_wait1()  { asm volatile("cp.async.wait_group 1;\n"); }

__device__ __forceinline__ void ldsm4(uint32_t& r0, uint32_t& r1, uint32_t& r2, uint32_t& r3,
                                      uint32_t addr) {
    asm volatile("ldmatrix.sync.aligned.m8n8.x4.shared.b16 {%0,%1,%2,%3}, [%4];\n"
                 : "=r"(r0), "=r"(r1), "=r"(r2), "=r"(r3) : "r"(addr));
}
__device__ __forceinline__ void mma16816(float c[4], uint32_t a0, uint32_t a1, uint32_t a2,
                                         uint32_t a3, uint32_t b0, uint32_t b1) {
    asm("mma.sync.aligned.m16n8k16.row.col.f32.f16.f16.f32 "
        "{%0,%1,%2,%3}, {%4,%5,%6,%7}, {%8,%9}, {%0,%1,%2,%3};\n"
        : "+f"(c[0]), "+f"(c[1]), "+f"(c[2]), "+f"(c[3])
        : "r"(a0), "r"(a1), "r"(a2), "r"(a3), "r"(b0), "r"(b1));
}

// SW128 swizzle for 128-byte rows: XOR row parity into byte-col bits [6:4]
#define SW128(off) ((off) ^ (((off) >> 3) & 0x70))

#define BM 128
#define BN 128
#define BK 64
#define STAGES 3
#define STAGE_BYTES (BM * BK * 2)              // 16384 (same for A and B)
#define SMEM_BYTES (STAGES * 2 * STAGE_BYTES)  // 98304

// ---------------- kernel 0a: fp32 -> fp16 copy ----------------
__global__ void f2h_kernel(const float4* __restrict__ src, uint2* __restrict__ dst, int n4) {
    int i = blockIdx.x * blockDim.x + threadIdx.x;
    if (i >= n4) return;
    float4 v = src[i];
    __half2 h0 = __floats2half2_rn(v.x, v.y);
    __half2 h1 = __floats2half2_rn(v.z, v.w);
    uint2 o;
    o.x = *reinterpret_cast<unsigned*>(&h0);
    o.y = *reinterpret_cast<unsigned*>(&h1);
    dst[i] = o;
}

// ---------------- kernel 0b: v [NBANK][ODIM] -> fp16 vT [ODIM][NBANK] ----------------
__global__ void transpose_f2h_kernel(const float* __restrict__ v, __half* __restrict__ vt) {
    __shared__ float tile[32][33];
    int bx = blockIdx.x * 32;
    int by = blockIdx.y * 32;
    int tx = threadIdx.x, ty = threadIdx.y;
#pragma unroll
    for (int j = 0; j < 32; j += 8)
        tile[ty + j][tx] = v[(size_t)(by + ty + j) * ODIM + bx + tx];
    __syncthreads();
#pragma unroll
    for (int j = 0; j < 32; j += 8)
        vt[(size_t)(bx + ty + j) * NBANK + by + tx] = __float2half(tile[tx][ty + j]);
}

// ---------------- GEMM1: Sh = fp16(q * k^T) + sumsq partials (UNCHANGED) --------------
__global__ void __launch_bounds__(256, 2) gemm1_kernel(
    const __half* __restrict__ A, const __half* __restrict__ B, __half* __restrict__ C,
    int K, int N, float* __restrict__ partials, int gridN) {
    extern __shared__ char smem[];
    const uint32_t sm = smem_u32(smem);
    const uint32_t smA = sm;
    const uint32_t smB = sm + STAGES * STAGE_BYTES;

    const int tid = threadIdx.x, lane = tid & 31, wid = tid >> 5;
    const int wm = wid >> 2, wn = wid & 3;
    const int bm = blockIdx.y * BM, bn = blockIdx.x * BN;

    float c[4][4][4];
#pragma unroll
    for (int a = 0; a < 4; a++)
#pragma unroll
        for (int b = 0; b < 4; b++)
#pragma unroll
            for (int i = 0; i < 4; i++) c[a][b][i] = 0.f;

    auto load_stage = [&](int s, int k0) {
        const uint32_t aBase = smA + s * STAGE_BYTES;
        const uint32_t bBase = smB + s * STAGE_BYTES;
#pragma unroll
        for (int i = 0; i < 4; i++) {
            int ch = tid + i * 256;
            int r = ch >> 3;
            int cb = (ch & 7) * 16;
            uint32_t ph = SW128((uint32_t)(r * 128 + cb));
            cp_async16(aBase + ph, A + (size_t)(bm + r) * K + k0 + (ch & 7) * 8);
            cp_async16(bBase + ph, B + (size_t)(bn + r) * K + k0 + (ch & 7) * 8);
        }
        cp_commit();
    };

    const int lr = lane & 15;
    const uint32_t hi = (uint32_t)(lane >> 4) * 16;
    const int rowA = wm * 64 + lr;
    const uint32_t swA = ((uint32_t)rowA & 7) << 4;
    const uint32_t aRow = smA + rowA * 128;
    const int rowB = wn * 32 + lr;
    const uint32_t swB = ((uint32_t)rowB & 7) << 4;
    const uint32_t bRow = smB + rowB * 128;

    const int NT = K / BK;
    load_stage(0, 0);
    load_stage(1, BK);

    for (int kt = 0; kt < NT; ++kt) {
        if (kt + 1 < NT) cp_wait1(); else cp_wait0();
        __syncthreads();
        if (kt + 2 < NT) load_stage((kt + 2) % STAGES, (kt + 2) * BK);

        const int s = kt % STAGES;
        const uint32_t aS = aRow + s * STAGE_BYTES;
        const uint32_t bS = bRow + s * STAGE_BYTES;
#pragma unroll
        for (int ks = 0; ks < 4; ++ks) {
            const uint32_t col = (uint32_t)(ks * 32) + hi;
            uint32_t a[4][4], b[4][2];
#pragma unroll
            for (int mt = 0; mt < 4; ++mt)
                ldsm4(a[mt][0], a[mt][1], a[mt][2], a[mt][3],
                      aS + mt * 2048 + (col ^ swA));
#pragma unroll
            for (int bt = 0; bt < 2; ++bt) {
                uint32_t t0, t1, t2, t3;
                ldsm4(t0, t1, t2, t3, bS + bt * 2048 + (col ^ swB));
                b[bt * 2 + 0][0] = t0; b[bt * 2 + 0][1] = t2;
                b[bt * 2 + 1][0] = t1; b[bt * 2 + 1][1] = t3;
            }
#pragma unroll
            for (int mt = 0; mt < 4; ++mt)
#pragma unroll
                for (int nt = 0; nt < 4; ++nt)
                    mma16816(c[mt][nt], a[mt][0], a[mt][1], a[mt][2], a[mt][3],
                             b[nt][0], b[nt][1]);
        }
    }

    const int rowBase = bm + wm * 64;
    const int colBase = bn + wn * 32;
#pragma unroll
    for (int mt = 0; mt < 4; ++mt) {
#pragma unroll
        for (int nt = 0; nt < 4; ++nt) {
            int row = rowBase + mt * 16 + (lane >> 2);
            int col = colBase + nt * 8 + (lane & 3) * 2;
            __half2* p0 = reinterpret_cast<__half2*>(C + (size_t)row * N + col);
            __half2* p1 = reinterpret_cast<__half2*>(C + (size_t)(row + 8) * N + col);
            *p0 = __floats2half2_rn(c[mt][nt][0], c[mt][nt][1]);
            *p1 = __floats2half2_rn(c[mt][nt][2], c[mt][nt][3]);
        }
    }

    {   // sumsq epilogue
        float acc[4][2];
#pragma unroll
        for (int mt = 0; mt < 4; ++mt) { acc[mt][0] = 0.f; acc[mt][1] = 0.f; }
#pragma unroll
        for (int mt = 0; mt < 4; ++mt)
#pragma unroll
            for (int nt = 0; nt < 4; ++nt) {
                acc[mt][0] += c[mt][nt][0] * c[mt][nt][0] + c[mt][nt][1] * c[mt][nt][1];
                acc[mt][1] += c[mt][nt][2] * c[mt][nt][2] + c[mt][nt][3] * c[mt][nt][3];
            }
#pragma unroll
        for (int o = 1; o < 4; o <<= 1)
#pragma unroll
            for (int mt = 0; mt < 4; ++mt) {
                acc[mt][0] += __shfl_xor_sync(0xffffffffu, acc[mt][0], o);
                acc[mt][1] += __shfl_xor_sync(0xffffffffu, acc[mt][1], o);
            }
        float* red = reinterpret_cast<float*>(smem);
        __syncthreads();
        if ((lane & 3) == 0) {
            int rq = lane >> 2;
#pragma unroll
            for (int mt = 0; mt < 4; ++mt) {
                red[wn * 128 + wm * 64 + mt * 16 + rq]     = acc[mt][0];
                red[wn * 128 + wm * 64 + mt * 16 + 8 + rq] = acc[mt][1];
            }
        }
        __syncthreads();
        if (tid < BM) {
            float s = red[tid] + red[128 + tid] + red[256 + tid] + red[384 + tid];
            partials[(size_t)(bm + tid) * gridN + blockIdx.x] = s;
        }
    }
}

// ---------------- GEMM2: persistent, statically balanced, RED epilogue ----------------
// out (pre-zeroed) accumulates every coverer's contribution via atomicAdd. With
// P <= 512, each CTA's unit range >= 128 so every tile has <= 2 coverers; fp32
// a+b == b+a bitwise -> deterministic regardless of arrival order.
__global__ void __launch_bounds__(256, 2) gemm2_persist_kernel(
    const __half* __restrict__ A, const __half* __restrict__ B,
    float* __restrict__ OUT, int P) {
    extern __shared__ char smem[];
    const uint32_t sm = smem_u32(smem);
    const uint32_t smA = sm;
    const uint32_t smB = sm + STAGES * STAGE_BYTES;

    const int tid = threadIdx.x, lane = tid & 31, wid = tid >> 5;
    const int wm = wid >> 2, wn = wid & 3;

    const int lr = lane & 15;
    const uint32_t hi = (uint32_t)(lane >> 4) * 16;
    const int rowAl = wm * 64 + lr;
    const uint32_t swA = ((uint32_t)rowAl & 7) << 4;
    const uint32_t aRow = smA + rowAl * 128;
    const int rowBl = wn * 32 + lr;
    const uint32_t swB = ((uint32_t)rowBl & 7) << 4;
    const uint32_t bRow = smB + rowBl * 128;

    long long u0 = (G2_UNITS * blockIdx.x) / P;
    const long long u1 = (G2_UNITS * (blockIdx.x + 1)) / P;

    while (u0 < u1) {
        const int t   = (int)(u0 >> 7);
        const int k0  = (int)(u0 & 127);
        int nkt = 128 - k0;
        if (u0 + nkt > u1) nkt = (int)(u1 - u0);
        const int bm = (t >> 3) * BM;
        const int bn = (t & 7) * BN;
        const __half* Aseg = A + (size_t)k0 * BK;
        const __half* Bseg = B + (size_t)k0 * BK;

        float c[4][4][4];
#pragma unroll
        for (int a = 0; a < 4; a++)
#pragma unroll
            for (int b = 0; b < 4; b++)
#pragma unroll
                for (int i = 0; i < 4; i++) c[a][b][i] = 0.f;

        auto load_stage = [&](int s, int kk) {
            const uint32_t aBase = smA + s * STAGE_BYTES;
            const uint32_t bBase = smB + s * STAGE_BYTES;
#pragma unroll
            for (int i = 0; i < 4; i++) {
                int ch = tid + i * 256;
                int r = ch >> 3;
                int cb = (ch & 7) * 16;
                uint32_t ph = SW128((uint32_t)(r * 128 + cb));
                cp_async16_pf(aBase + ph, Aseg + (size_t)(bm + r) * NBANK + kk * BK + (ch & 7) * 8);
                cp_async16_pf(bBase + ph, Bseg + (size_t)(bn + r) * NBANK + kk * BK + (ch & 7) * 8);
            }
            cp_commit();
        };

        load_stage(0, 0);
        if (nkt > 1) load_stage(1, 1);

        for (int kt = 0; kt < nkt; ++kt) {
            if (kt + 1 < nkt) cp_wait1(); else cp_wait0();
            __syncthreads();
            if (kt + 2 < nkt) load_stage((kt + 2) % STAGES, kt + 2);

            const int s = kt % STAGES;
            const uint32_t aS = aRow + s * STAGE_BYTES;
            const uint32_t bS = bRow + s * STAGE_BYTES;
#pragma unroll
            for (int ks = 0; ks < 4; ++ks) {
                const uint32_t col = (uint32_t)(ks * 32) + hi;
                uint32_t a[4][4], b[4][2];
#pragma unroll
                for (int mt = 0; mt < 4; ++mt)
                    ldsm4(a[mt][0], a[mt][1], a[mt][2], a[mt][3],
                          aS + mt * 2048 + (col ^ swA));
#pragma unroll
                for (int bt = 0; bt < 2; ++bt) {
                    uint32_t t0, t1, t2, t3;
                    ldsm4(t0, t1, t2, t3, bS + bt * 2048 + (col ^ swB));
                    b[bt * 2 + 0][0] = t0; b[bt * 2 + 0][1] = t2;
                    b[bt * 2 + 1][0] = t1; b[bt * 2 + 1][1] = t3;
                }
#pragma unroll
                for (int mt = 0; mt < 4; ++mt)
#pragma unroll
                    for (int nt = 0; nt < 4; ++nt)
                        mma16816(c[mt][nt], a[mt][0], a[mt][1], a[mt][2], a[mt][3],
                                 b[nt][0], b[nt][1]);
            }
        }
        __syncthreads();  // smem reuse safety before next segment's loads

        // epilogue: accumulate into pre-zeroed OUT (<=2 coverers; commutative-exact)
        const int rowBase = bm + wm * 64;
        const int colBase = bn + wn * 32;
#pragma unroll
        for (int mt = 0; mt < 4; ++mt) {
#pragma unroll
            for (int nt = 0; nt < 4; ++nt) {
                int row = rowBase + mt * 16 + (lane >> 2);
                int col = colBase + nt * 8 + (lane & 3) * 2;
                float* p0 = OUT + (size_t)row * ODIM + col;
                float* p1 = OUT + (size_t)(row + 8) * ODIM + col;
                atomicAdd(p0,     c[mt][nt][0]);
                atomicAdd(p0 + 1, c[mt][nt][1]);
                atomicAdd(p1,     c[mt][nt][2]);
                atomicAdd(p1 + 1, c[mt][nt][3]);
            }
        }

        u0 += nkt;
    }
}

// ---------------- kernel 2: row norms ----------------
__global__ void rownorm_kernel(const float* __restrict__ partials, float* __restrict__ invnorm,
                               int gridN) {
    int row = blockIdx.x * blockDim.x + threadIdx.x;
    if (row >= MDIM) return;
    float s = 0.f;
    for (int j = 0; j < gridN; j++) s += partials[(size_t)row * gridN + j];
    invnorm[row] = sqrtf((float)NBANK) * rsqrtf(s);
}

// ---------------- kernel 3: G = fp16(gelu(Sh * invnorm[row])), 8 halves/thread --------
__global__ void gelu_kernel(const uint4* __restrict__ S, uint4* __restrict__ G,
                            const float* __restrict__ invnorm, int n8) {
    int i = blockIdx.x * blockDim.x + threadIdx.x;
    if (i >= n8) return;
    float sc = invnorm[i >> 10];  // NBANK/8 = 1024 uint4 per row
    uint4 x = S[i];
    uint4 o;
    unsigned* xi = reinterpret_cast<unsigned*>(&x);
    unsigned* oi = reinterpret_cast<unsigned*>(&o);
#pragma unroll
    for (int j = 0; j < 4; j++) {
        __half2 h = *reinterpret_cast<__half2*>(&xi[j]);
        float a0 = __low2float(h) * sc;
        float a1 = __high2float(h) * sc;
        float g0 = a0 * normcdff(a0);  // exact GELU: x * Phi(x)
        float g1 = a1 * normcdff(a1);
        __half2 r = __floats2half2_rn(g0, g1);
        oi[j] = *reinterpret_cast<unsigned*>(&r);
    }
    G[i] = o;
}

// ---------------- launch ----------------
extern "C" void kernel_launch(void* const* d_in, const int* in_sizes, int n_in,
                              void* d_out, int out_size) {
    const float* q = (const float*)d_in[0];
    const float* k = (const float*)d_in[1];
    const float* v = (const float*)d_in[2];
    float* out = (float*)d_out;

    __half *qh, *kh, *vt, *Sh, *G;
    float *partials, *invn;
    cudaGetSymbolAddress((void**)&qh, g_qh);
    cudaGetSymbolAddress((void**)&kh, g_kh);
    cudaGetSymbolAddress((void**)&vt, g_vhT);
    cudaGetSymbolAddress((void**)&Sh, g_Sh);
    cudaGetSymbolAddress((void**)&G, g_G);
    cudaGetSymbolAddress((void**)&partials, g_partials);
    cudaGetSymbolAddress((void**)&invn, g_invnorm);

    int nsm = 148;
    cudaDeviceGetAttribute(&nsm, cudaDevAttrMultiProcessorCount, 0);
    int P = 2 * nsm;            // all persistent CTAs resident (2/SM)
    if (P > 512) P = 512;       // keep segment length >= 128 (<= 2 coverers/tile)

    cudaFuncSetAttribute((const void*)gemm1_kernel,
                         cudaFuncAttributeMaxDynamicSharedMemorySize, SMEM_BYTES);
    cudaFuncSetAttribute((const void*)gemm2_persist_kernel,
                         cudaFuncAttributeMaxDynamicSharedMemorySize, SMEM_BYTES);

    // 0) input conversion
    const int QN4 = MDIM * KDIM / 4;
    const int KN4 = NBANK * KDIM / 4;
    f2h_kernel<<<(QN4 + 255) / 256, 256>>>((const float4*)q, (uint2*)qh, QN4);
    f2h_kernel<<<(KN4 + 255) / 256, 256>>>((const float4*)k, (uint2*)kh, KN4);
    transpose_f2h_kernel<<<dim3(ODIM / 32, NBANK / 32), dim3(32, 8)>>>(v, vt);

    // zero the output (graph-legal memset node); GEMM2 accumulates into it
    cudaMemsetAsync(out, 0, (size_t)MDIM * ODIM * sizeof(float));

    // 1) Sh = fp16(q * k^T), + per-tile sumsq partials (from fp32 accumulators)
    gemm1_kernel<<<dim3(NBANK / BN, MDIM / BM), 256, SMEM_BYTES>>>(
        qh, kh, Sh, KDIM, NBANK, partials, G1_GRIDN);

    // 2) row inverse norms (deterministic fixed-order sum)
    rownorm_kernel<<<MDIM / 256, 256>>>(partials, invn, G1_GRIDN);

    // 3) G = fp16(gelu(Sh * invnorm))
    const int SN8 = (int)((size_t)MDIM * NBANK / 8);
    gelu_kernel<<<(SN8 + 255) / 256, 256>>>((const uint4*)Sh, (uint4*)G, invn, SN8);

    // 4) out += G * v (persistent, statically K-balanced, RED epilogue)
    gemm2_persist_kernel<<<P, 256, SMEM_BYTES>>>(G, vt, out, P);
}